// round 7
// baseline (speedup 1.0000x reference)
#include <cuda_runtime.h>
#include <math.h>

#define NNODES 50000
#define NEDGES 800000
#define CSR_BLOCKS 148
#define CSR_THREADS 512
#define NPB ((NNODES + CSR_BLOCKS - 1) / CSR_BLOCKS)   // 338

// ---------------- scratch (zero-initialized at module load) ----------------
__device__ int g_counts[NNODES];       // invariant: zero at entry of every call
__device__ int g_offsets[NNODES + 1];
__device__ int g_cursor[NNODES];
__device__ int g_edge_ids[NEDGES];
__device__ int g_bsum[CSR_BLOCKS];
__device__ int g_s1, g_s2, g_s3;       // barrier counters; reset by attn_kernel

// grid barrier: all CSR_BLOCKS blocks are co-resident (grid == #SMs)
__device__ __forceinline__ void grid_barrier(int* ctr, int t) {
    __syncthreads();
    if (t == 0) {
        __threadfence();
        atomicAdd(ctr, 1);
        while (((volatile int*)ctr)[0] < CSR_BLOCKS) { }
        __threadfence();
    }
    __syncthreads();
}

// ---------------- 1. persistent fused CSR build: count + scan + scatter ----------------
__global__ void __launch_bounds__(CSR_THREADS) csr_fused_kernel(const int* __restrict__ dst) {
    __shared__ int warp_sums[CSR_THREADS / 32];   // 16
    __shared__ int s_base;
    int t = threadIdx.x, b = blockIdx.x;
    int lane = t & 31, w = t >> 5;
    const int NQ = NEDGES / 4;
    const int STRIDE = CSR_BLOCKS * CSR_THREADS;

    // ---- Phase A: histogram (int4 grid-stride) ----
    for (int i = b * CSR_THREADS + t; i < NQ; i += STRIDE) {
        int4 d = reinterpret_cast<const int4*>(dst)[i];
        atomicAdd(&g_counts[d.x], 1);
        atomicAdd(&g_counts[d.y], 1);
        atomicAdd(&g_counts[d.z], 1);
        atomicAdd(&g_counts[d.w], 1);
    }
    grid_barrier(&g_s1, t);

    // ---- Phase B: block scan of this block's NPB-node slice ----
    int node = b * NPB + t;
    int c = (t < NPB && node < NNODES) ? g_counts[node] : 0;
    int v = c;
    #pragma unroll
    for (int o = 1; o < 32; o <<= 1) {
        int u = __shfl_up_sync(0xFFFFFFFFu, v, o);
        if (lane >= o) v += u;
    }
    if (lane == 31) warp_sums[w] = v;
    __syncthreads();
    if (w == 0) {
        int ws = (lane < 16) ? warp_sums[lane] : 0;
        #pragma unroll
        for (int o = 1; o < 16; o <<= 1) {
            int u = __shfl_up_sync(0xFFFFFFFFu, ws, o);
            if (lane >= o) ws += u;
        }
        if (lane < 16) warp_sums[lane] = ws;
    }
    __syncthreads();
    int incl = v + ((w > 0) ? warp_sums[w - 1] : 0);
    if (t == 0) g_bsum[b] = warp_sums[15];
    grid_barrier(&g_s2, t);

    // base = sum of predecessor block totals
    if (w == 0) {
        int agg = 0;
        for (int i = lane; i < b; i += 32) agg += g_bsum[i];
        #pragma unroll
        for (int o = 16; o > 0; o >>= 1)
            agg += __shfl_xor_sync(0xFFFFFFFFu, agg, o);
        if (lane == 0) s_base = agg;
    }
    __syncthreads();
    int exc = s_base + incl - c;
    if (t < NPB && node < NNODES) {
        g_offsets[node] = exc;
        g_cursor[node]  = exc;
        g_counts[node]  = 0;       // restore zero-invariant for next call
    }
    if (b == 0 && t == 0) g_offsets[NNODES] = NEDGES;
    grid_barrier(&g_s3, t);

    // ---- Phase C: scatter (dst re-read is L2-hot) ----
    for (int i = b * CSR_THREADS + t; i < NQ; i += STRIDE) {
        int4 d = reinterpret_cast<const int4*>(dst)[i];
        int e = i * 4;
        g_edge_ids[atomicAdd(&g_cursor[d.x], 1)] = e;
        g_edge_ids[atomicAdd(&g_cursor[d.y], 1)] = e + 1;
        g_edge_ids[atomicAdd(&g_cursor[d.z], 1)] = e + 2;
        g_edge_ids[atomicAdd(&g_cursor[d.w], 1)] = e + 3;
    }
}

// ---------------- 2. fused warp-per-node, x2 unroll, 4 blocks/SM ----------------
// Lane l owns flat floats [8l, 8l+8) of each 256-float row (head h = l>>2).
// Single pass: s += exp(score); acc += exp(score)*v; out = acc/s.
__global__ void __launch_bounds__(256, 4) attn_kernel(
    const float* __restrict__ key,
    const float* __restrict__ q0g,
    const float* __restrict__ q1g,
    const float* __restrict__ value,
    float* __restrict__ out)
{
    // reset CSR barrier counters for the next replay (nothing here reads them;
    // the launch boundary orders these stores before the next csr_fused call)
    if (blockIdx.x == 0 && threadIdx.x == 0) {
        g_s1 = 0; g_s2 = 0; g_s3 = 0;
    }

    int n = (blockIdx.x * blockDim.x + threadIdx.x) >> 5;
    int lane = threadIdx.x & 31;
    if (n >= NNODES) return;

    // lane's 8 q floats: channels c = 2*lane, 2*lane+1
    float q[8];
    {
        float2 a0 = reinterpret_cast<const float2*>(q0g + (size_t)n * 64)[lane];
        const float2* p1 = reinterpret_cast<const float2*>(
            q1g + (size_t)n * 192 + 6 * lane);
        float2 b0 = p1[0], b1 = p1[1], b2 = p1[2];
        q[0] = a0.x; q[1] = b0.x; q[2] = b0.y; q[3] = b1.x;
        q[4] = a0.y; q[5] = b1.y; q[6] = b2.x; q[7] = b2.y;
    }

    int start = g_offsets[n];
    int end   = g_offsets[n + 1];

    float4 acc0 = make_float4(0.f, 0.f, 0.f, 0.f);
    float4 acc1 = make_float4(0.f, 0.f, 0.f, 0.f);
    float s = 0.0f;
    int lane2 = lane * 2;

    int idx = start;
    for (; idx + 2 <= end; idx += 2) {
        int e0 = g_edge_ids[idx];
        int e1 = g_edge_ids[idx + 1];

        const float4* kp0 = reinterpret_cast<const float4*>(key + (size_t)e0 * 256) + lane2;
        const float4* kp1 = reinterpret_cast<const float4*>(key + (size_t)e1 * 256) + lane2;
        const float4* vp0 = reinterpret_cast<const float4*>(value + (size_t)e0 * 256) + lane2;
        const float4* vp1 = reinterpret_cast<const float4*>(value + (size_t)e1 * 256) + lane2;
        float4 ka0 = __ldcs(kp0), ka1 = __ldcs(kp0 + 1);
        float4 kb0 = __ldcs(kp1), kb1 = __ldcs(kp1 + 1);
        float4 va0 = __ldcs(vp0), va1 = __ldcs(vp0 + 1);
        float4 vb0 = __ldcs(vp1), vb1 = __ldcs(vp1 + 1);

        float p0 = ka0.x*q[0] + ka0.y*q[1] + ka0.z*q[2] + ka0.w*q[3]
                 + ka1.x*q[4] + ka1.y*q[5] + ka1.z*q[6] + ka1.w*q[7];
        float p1 = kb0.x*q[0] + kb0.y*q[1] + kb0.z*q[2] + kb0.w*q[3]
                 + kb1.x*q[4] + kb1.y*q[5] + kb1.z*q[6] + kb1.w*q[7];
        p0 += __shfl_xor_sync(0xFFFFFFFFu, p0, 1);
        p1 += __shfl_xor_sync(0xFFFFFFFFu, p1, 1);
        p0 += __shfl_xor_sync(0xFFFFFFFFu, p0, 2);
        p1 += __shfl_xor_sync(0xFFFFFFFFu, p1, 2);
        float ex0 = __expf(p0 * 0.0625f);
        float ex1 = __expf(p1 * 0.0625f);
        s += ex0 + ex1;

        acc0.x += ex0*va0.x + ex1*vb0.x;  acc0.y += ex0*va0.y + ex1*vb0.y;
        acc0.z += ex0*va0.z + ex1*vb0.z;  acc0.w += ex0*va0.w + ex1*vb0.w;
        acc1.x += ex0*va1.x + ex1*vb1.x;  acc1.y += ex0*va1.y + ex1*vb1.y;
        acc1.z += ex0*va1.z + ex1*vb1.z;  acc1.w += ex0*va1.w + ex1*vb1.w;
    }
    if (idx < end) {   // remainder
        int e0 = g_edge_ids[idx];
        const float4* kp0 = reinterpret_cast<const float4*>(key + (size_t)e0 * 256) + lane2;
        const float4* vp0 = reinterpret_cast<const float4*>(value + (size_t)e0 * 256) + lane2;
        float4 ka0 = __ldcs(kp0), ka1 = __ldcs(kp0 + 1);
        float4 va0 = __ldcs(vp0), va1 = __ldcs(vp0 + 1);
        float p0 = ka0.x*q[0] + ka0.y*q[1] + ka0.z*q[2] + ka0.w*q[3]
                 + ka1.x*q[4] + ka1.y*q[5] + ka1.z*q[6] + ka1.w*q[7];
        p0 += __shfl_xor_sync(0xFFFFFFFFu, p0, 1);
        p0 += __shfl_xor_sync(0xFFFFFFFFu, p0, 2);
        float ex0 = __expf(p0 * 0.0625f);
        s += ex0;
        acc0.x += ex0*va0.x; acc0.y += ex0*va0.y; acc0.z += ex0*va0.z; acc0.w += ex0*va0.w;
        acc1.x += ex0*va1.x; acc1.y += ex0*va1.y; acc1.z += ex0*va1.z; acc1.w += ex0*va1.w;
    }

    float inv = (end > start) ? 1.0f / s : 0.0f;
    acc0.x *= inv; acc0.y *= inv; acc0.z *= inv; acc0.w *= inv;
    acc1.x *= inv; acc1.y *= inv; acc1.z *= inv; acc1.w *= inv;

    float4* op = reinterpret_cast<float4*>(out + (size_t)n * 256) + lane2;
    op[0] = acc0;
    op[1] = acc1;
}

// ---------------- launch ----------------
extern "C" void kernel_launch(void* const* d_in, const int* in_sizes, int n_in,
                              void* d_out, int out_size) {
    const float* key_edge = (const float*)d_in[0];  // [E, 8, 32]
    const float* query_0  = (const float*)d_in[1];  // [N, 64, 1]
    const float* query_1  = (const float*)d_in[2];  // [N, 64, 3]
    const float* value    = (const float*)d_in[3];  // [E, 64, 4]
    const int*   dst      = (const int*)d_in[4];    // [E]
    float* out = (float*)d_out;                     // [N, 64, 4]

    csr_fused_kernel<<<CSR_BLOCKS, CSR_THREADS>>>(dst);
    attn_kernel<<<(NNODES * 32 + 255) / 256, 256>>>(
        key_edge, query_0, query_1, value, out);
}